// round 15
// baseline (speedup 1.0000x reference)
#include <cuda_runtime.h>
#include <cuda_bf16.h>
#include <cstdint>
#include <math.h>

// Problem constants (fixed by setup_inputs)
#define T_TOK 2048
#define H_DIM 2048
#define I_DIM 4096
#define E_NUM 8

// ---------------------------------------------------------------------------
// bf16 hi/lo pre-split scratch (static device allocations are allowed)
// ---------------------------------------------------------------------------
__device__ __nv_bfloat16 g_x_hi[(size_t)T_TOK * H_DIM];
__device__ __nv_bfloat16 g_x_lo[(size_t)T_TOK * H_DIM];
__device__ __nv_bfloat16 g_eg_hi[(size_t)E_NUM * I_DIM * H_DIM];
__device__ __nv_bfloat16 g_eg_lo[(size_t)E_NUM * I_DIM * H_DIM];
__device__ __nv_bfloat16 g_eu_hi[(size_t)E_NUM * I_DIM * H_DIM];
__device__ __nv_bfloat16 g_eu_lo[(size_t)E_NUM * I_DIM * H_DIM];
__device__ __nv_bfloat16 g_ed_hi[(size_t)E_NUM * H_DIM * I_DIM];
__device__ __nv_bfloat16 g_ed_lo[(size_t)E_NUM * H_DIM * I_DIM];
__device__ __nv_bfloat16 g_sg_hi[(size_t)I_DIM * H_DIM];
__device__ __nv_bfloat16 g_sg_lo[(size_t)I_DIM * H_DIM];
__device__ __nv_bfloat16 g_su_hi[(size_t)I_DIM * H_DIM];
__device__ __nv_bfloat16 g_su_lo[(size_t)I_DIM * H_DIM];
__device__ __nv_bfloat16 g_sd_hi[(size_t)H_DIM * I_DIM];
__device__ __nv_bfloat16 g_sd_lo[(size_t)H_DIM * I_DIM];
__device__ __nv_bfloat16 g_hs_hi[(size_t)T_TOK * I_DIM];
__device__ __nv_bfloat16 g_hs_lo[(size_t)T_TOK * I_DIM];
__device__ __nv_bfloat16 g_hr_hi[(size_t)T_TOK * I_DIM];
__device__ __nv_bfloat16 g_hr_lo[(size_t)T_TOK * I_DIM];

__device__ int   g_sel[T_TOK];
__device__ float g_score[T_TOK];
__device__ int   g_perm[T_TOK];
__device__ int   g_off[E_NUM + 1];

// ===========================================================================
// PTX helpers (arch-agnostic tensor path; tcgen05 rejected by the toolchain's
// sm_103 ptxas target)
// ===========================================================================
__device__ __forceinline__ void mma_bf16(float* c, const uint32_t* a, const uint32_t* b) {
    asm volatile(
        "mma.sync.aligned.m16n8k16.row.col.f32.bf16.bf16.f32 "
        "{%0,%1,%2,%3}, {%4,%5,%6,%7}, {%8,%9}, {%0,%1,%2,%3};"
        : "+f"(c[0]), "+f"(c[1]), "+f"(c[2]), "+f"(c[3])
        : "r"(a[0]), "r"(a[1]), "r"(a[2]), "r"(a[3]), "r"(b[0]), "r"(b[1]));
}

__device__ __forceinline__ void ldm_x4(uint32_t* r, uint32_t addr) {
    asm volatile("ldmatrix.sync.aligned.m8n8.x4.shared.b16 {%0,%1,%2,%3}, [%4];"
        : "=r"(r[0]), "=r"(r[1]), "=r"(r[2]), "=r"(r[3]) : "r"(addr));
}

__device__ __forceinline__ uint32_t smem_u32(const void* p) {
    uint32_t a;
    asm("{ .reg .u64 t; cvta.to.shared.u64 t, %1; cvt.u32.u64 %0, t; }"
        : "=r"(a) : "l"(p));
    return a;
}

__device__ __forceinline__ void cp16(uint32_t dst, const void* src, int sz) {
    asm volatile("cp.async.cg.shared.global [%0], [%1], 16, %2;"
        :: "r"(dst), "l"(src), "r"(sz));
}
__device__ __forceinline__ void cp_commit() {
    asm volatile("cp.async.commit_group;" ::: "memory");
}
template<int N>
__device__ __forceinline__ void cp_wait() {
    asm volatile("cp.async.wait_group %0;" :: "n"(N) : "memory");
}

// Tile rows are 128B: 16B blocks 0-3 = bf16 hi (k 0..31), 4-7 = bf16 lo.
// Physical block = logical block ^ (row & 7) -> conflict-free ldmatrix/STS.
__device__ __forceinline__ uint32_t swadr(uint32_t tile, int row, int blk) {
    return tile + (uint32_t)(row * 128) + (uint32_t)((blk ^ (row & 7)) * 16);
}

__device__ __forceinline__ uint32_t pack_hi2(float a, float b, float* la, float* lb) {
    __nv_bfloat16 ha = __float2bfloat16_rn(a);
    __nv_bfloat16 hb = __float2bfloat16_rn(b);
    *la = a - __bfloat162float(ha);
    *lb = b - __bfloat162float(hb);
    return (uint32_t)__bfloat16_as_ushort(ha) | ((uint32_t)__bfloat16_as_ushort(hb) << 16);
}
__device__ __forceinline__ uint32_t pack_lo2(float a, float b) {
    return (uint32_t)__bfloat16_as_ushort(__float2bfloat16_rn(a))
         | ((uint32_t)__bfloat16_as_ushort(__float2bfloat16_rn(b)) << 16);
}

// ===========================================================================
// Operand pre-split: fp32 -> bf16 hi + bf16 lo. 16 floats/thread, MLP=4.
// ===========================================================================
__global__ void split_kernel(const float* __restrict__ src,
                             __nv_bfloat16* __restrict__ hi,
                             __nv_bfloat16* __restrict__ lo, int n16) {
    int i = blockIdx.x * blockDim.x + threadIdx.x;
    if (i >= n16) return;
    const float4* s = (const float4*)src + 4 * (size_t)i;
    float4 v[4];
#pragma unroll
    for (int j = 0; j < 4; j++) v[j] = s[j];

    uint4 h[2], l[2];
#pragma unroll
    for (int j = 0; j < 2; j++) {
        float l0, l1, l2, l3, l4, l5, l6, l7;
        h[j].x = pack_hi2(v[2 * j].x,     v[2 * j].y,     &l0, &l1);
        h[j].y = pack_hi2(v[2 * j].z,     v[2 * j].w,     &l2, &l3);
        h[j].z = pack_hi2(v[2 * j + 1].x, v[2 * j + 1].y, &l4, &l5);
        h[j].w = pack_hi2(v[2 * j + 1].z, v[2 * j + 1].w, &l6, &l7);
        l[j].x = pack_lo2(l0, l1);
        l[j].y = pack_lo2(l2, l3);
        l[j].z = pack_lo2(l4, l5);
        l[j].w = pack_lo2(l6, l7);
    }
    uint4* ph = (uint4*)(hi + 16 * (size_t)i);
    uint4* pl = (uint4*)(lo + 16 * (size_t)i);
    ph[0] = h[0]; ph[1] = h[1];
    pl[0] = l[0]; pl[1] = l[1];
}

// ===========================================================================
// Router + grouping (proven)
// ===========================================================================
__global__ void router_kernel(const float* __restrict__ x,
                              const float* __restrict__ rw,
                              float* __restrict__ scores_out) {
    int warps_per_block = blockDim.x >> 5;
    int t = blockIdx.x * warps_per_block + (threadIdx.x >> 5);
    int lane = threadIdx.x & 31;
    if (t >= T_TOK) return;

    float acc[E_NUM];
#pragma unroll
    for (int e = 0; e < E_NUM; e++) acc[e] = 0.f;

    const float* xr = x + (size_t)t * H_DIM;
    for (int k = lane; k < H_DIM; k += 32) {
        float xv = xr[k];
#pragma unroll
        for (int e = 0; e < E_NUM; e++) acc[e] += xv * rw[e * H_DIM + k];
    }
#pragma unroll
    for (int e = 0; e < E_NUM; e++) {
#pragma unroll
        for (int o = 16; o > 0; o >>= 1)
            acc[e] += __shfl_xor_sync(0xFFFFFFFFu, acc[e], o);
    }
    if (lane == 0) {
        int best = 0;
        float bv = acc[0];
#pragma unroll
        for (int e = 1; e < E_NUM; e++)
            if (acc[e] > bv) { bv = acc[e]; best = e; }
        float s = 1.f / (1.f + expf(-bv));
        g_sel[t] = best;
        g_score[t] = s;
#pragma unroll
        for (int e = 0; e < E_NUM; e++)
            scores_out[(size_t)e * T_TOK + t] = (e == best) ? s : 0.f;
    }
}

__global__ void group_kernel() {
    __shared__ int cnt[E_NUM];
    __shared__ int cur[E_NUM];
    int tid = threadIdx.x;
    if (tid < E_NUM) cnt[tid] = 0;
    __syncthreads();
    for (int t = tid; t < T_TOK; t += blockDim.x)
        atomicAdd(&cnt[g_sel[t]], 1);
    __syncthreads();
    if (tid == 0) {
        int run = 0;
        for (int e = 0; e < E_NUM; e++) {
            g_off[e] = run; cur[e] = run; run += cnt[e];
        }
        g_off[E_NUM] = run;
    }
    __syncthreads();
    for (int t = tid; t < T_TOK; t += blockDim.x) {
        int p = atomicAdd(&cur[g_sel[t]], 1);
        g_perm[p] = t;
    }
}

// ===========================================================================
// GEMM engine: cp.async pipeline (NST stages), ldmatrix, mma.sync bf16 3-term.
//   EPI=0 (gateup): W0=gate, W1=up; out = silu(G)*U*(score) -> bf16 hi/lo
//   EPI=1 (down):   W0 only; out (+)= A.W^T  (fp32)
// Shared: BM=128 (4m x 2n warps), BN=64/128, 3-stage, 2 CTAs/SM  (R11-proven)
// Routed: BM=64  (2m x 4n warps), BN=128/256 (R15: wider n-tile -> 4:1
//   MMA:ldmatrix, halved A traffic/barriers), 2-stage, 2 CTAs/SM (80KB smem).
// Compute order = R11 (R13 reorder reverted). ebase: expert offset.
// ===========================================================================
template<int KD, int EPI, bool ROUTED, int BM, int BN, int NST>
__global__ void __launch_bounds__(256, 2)
moe_gemm(const __nv_bfloat16* __restrict__ Ahi,
         const __nv_bfloat16* __restrict__ Alo,
         const __nv_bfloat16* __restrict__ W0hb,
         const __nv_bfloat16* __restrict__ W0lb,
         const __nv_bfloat16* __restrict__ W1hb,
         const __nv_bfloat16* __restrict__ W1lb,
         __nv_bfloat16* __restrict__ OutHi,
         __nv_bfloat16* __restrict__ OutLo,
         float* __restrict__ OutF,
         int ebase) {
    constexpr int NMAT  = (EPI == 0) ? 2 : 1;
    constexpr int WM    = BM / 32;          // m-warps
    constexpr int WN    = 8 / WM;           // n-warps
    constexpr int NW    = BN / WN;          // n-cols per warp
    constexpr int NSUBW = NW / 8;           // 8-wide n-subtiles per warp
    constexpr int TA    = BM * 128;         // A-tile bytes per stage (hi+lo)
    constexpr int TW    = BN * 128;         // W bytes per matrix per stage
    constexpr int SBUF  = TA + NMAT * TW;
    constexpr int NIT   = KD / 32;
    constexpr int AJ    = BM / 32;          // A cp16 chunks per thread
    constexpr int WJ    = (NMAT * BN * 8) / 256;  // W cp16 chunks per thread

    extern __shared__ char smem_raw[];
    __shared__ int   arow[BM];
    __shared__ int   orow[BM];
    __shared__ float sscale[BM];

    const uint32_t raw_u = smem_u32(smem_raw);
    const uint32_t smem_u = (raw_u + 127) & ~127u;

    const int tid = threadIdx.x;
    const int e = ROUTED ? (ebase + blockIdx.z) : 0;
    int start = 0, mcnt = T_TOK;
    if (ROUTED) { start = g_off[e]; mcnt = g_off[e + 1] - start; }
    const int m0 = blockIdx.x * BM;          // m fastest-varying (L2 weight reuse)
    if (ROUTED && m0 >= mcnt) return;
    const int n0 = blockIdx.y * BN;

    size_t eo = ROUTED ? (size_t)e * ((EPI == 0) ? I_DIM : H_DIM) * KD : 0;
    const __nv_bfloat16* w0h = W0hb + eo + (size_t)n0 * KD;
    const __nv_bfloat16* w0l = W0lb + eo + (size_t)n0 * KD;
    const __nv_bfloat16* w1h = (EPI == 0) ? (W1hb + eo + (size_t)n0 * KD) : nullptr;
    const __nv_bfloat16* w1l = (EPI == 0) ? (W1lb + eo + (size_t)n0 * KD) : nullptr;

    if (tid < BM) {
        int r = m0 + tid;
        int a = -1, o = -1;
        float sc = 1.f;
        if (r < mcnt) {
            if (EPI == 0) {
                a = ROUTED ? g_perm[start + r] : r;
                o = ROUTED ? (start + r) : r;
                if (ROUTED) sc = g_score[a];
            } else {
                a = ROUTED ? (start + r) : r;
                o = ROUTED ? g_perm[start + r] : r;
            }
        }
        arow[tid] = a; orow[tid] = o; sscale[tid] = sc;
    }
    __syncthreads();

    const int lane = tid & 31;
    const int wid  = tid >> 5;
    const int wm   = wid % WM;
    const int wn   = wid / WM;

    float accG[2][NSUBW][4];
    float accU[(EPI == 0) ? 2 : 1][(EPI == 0) ? NSUBW : 1][4];
#pragma unroll
    for (int mi = 0; mi < 2; mi++)
#pragma unroll
        for (int nj = 0; nj < NSUBW; nj++)
#pragma unroll
            for (int c = 0; c < 4; c++) accG[mi][nj][c] = 0.f;
    if (EPI == 0) {
#pragma unroll
        for (int mi = 0; mi < 2; mi++)
#pragma unroll
            for (int nj = 0; nj < NSUBW; nj++)
#pragma unroll
                for (int c = 0; c < 4; c++) accU[mi][nj][c] = 0.f;
    }

    auto prefetch = [&](int it) {
        uint32_t sAu = smem_u + (it % NST) * SBUF;
        uint32_t sW0u = sAu + TA;
        int k0 = it * 32;
#pragma unroll
        for (int j = 0; j < AJ; j++) {
            int c = tid + 256 * j;
            int row = c >> 3, blk = c & 7;
            int tok = arow[row];
            const __nv_bfloat16* base = (blk < 4) ? Ahi : Alo;
            const __nv_bfloat16* src =
                base + (size_t)(tok < 0 ? 0 : tok) * KD + k0 + (blk & 3) * 8;
            cp16(swadr(sAu, row, blk), src, tok < 0 ? 0 : 16);
        }
#pragma unroll
        for (int j = 0; j < WJ; j++) {
            int c = tid + 256 * j;
            if (EPI == 0) {
                int mat = c / (BN * 8), cc = c % (BN * 8);
                int row = cc >> 3, blk = cc & 7;
                const __nv_bfloat16* base =
                    mat ? ((blk < 4) ? w1h : w1l) : ((blk < 4) ? w0h : w0l);
                cp16(swadr(sW0u + mat * TW, row, blk),
                     base + (size_t)row * KD + k0 + (blk & 3) * 8, 16);
            } else {
                int row = c >> 3, blk = c & 7;
                const __nv_bfloat16* base = (blk < 4) ? w0h : w0l;
                cp16(swadr(sW0u, row, blk),
                     base + (size_t)row * KD + k0 + (blk & 3) * 8, 16);
            }
        }
    };

    // R11-proven compute order.
    auto compute = [&](int buf) {
        const uint32_t sA  = smem_u + buf * SBUF;
        const uint32_t sW0 = sA + TA;
        const uint32_t sW1 = sW0 + TW;
        const int lr = lane & 7;
        const int t  = lane >> 3;
#pragma unroll
        for (int kk = 0; kk < 2; kk++) {
            const int kb = 2 * kk;
            uint32_t ah[2][4], al[2][4];
#pragma unroll
            for (int mi = 0; mi < 2; mi++) {
                int row = wm * 32 + mi * 16 + (t & 1) * 8 + lr;
                int blk = kb + (t >> 1);
                ldm_x4(ah[mi], swadr(sA, row, blk));
                ldm_x4(al[mi], swadr(sA, row, blk + 4));
            }
#pragma unroll
            for (int p = 0; p < NSUBW / 2; p++) {
                int n = wn * NW + p * 16 + (t >> 1) * 8 + lr;
                int blk = kb + (t & 1);
                uint32_t gh[4], gl[4];
                ldm_x4(gh, swadr(sW0, n, blk));
                ldm_x4(gl, swadr(sW0, n, blk + 4));
#pragma unroll
                for (int mi = 0; mi < 2; mi++) {
                    mma_bf16(accG[mi][2 * p],     ah[mi], gh);
                    mma_bf16(accG[mi][2 * p],     ah[mi], gl + 0);
                    mma_bf16(accG[mi][2 * p],     al[mi], gh);
                    mma_bf16(accG[mi][2 * p + 1], ah[mi], gh + 2);
                    mma_bf16(accG[mi][2 * p + 1], ah[mi], gl + 2);
                    mma_bf16(accG[mi][2 * p + 1], al[mi], gh + 2);
                }
                if (EPI == 0) {
                    uint32_t uh[4], ul[4];
                    ldm_x4(uh, swadr(sW1, n, blk));
                    ldm_x4(ul, swadr(sW1, n, blk + 4));
#pragma unroll
                    for (int mi = 0; mi < 2; mi++) {
                        mma_bf16(accU[mi][2 * p],     ah[mi], uh);
                        mma_bf16(accU[mi][2 * p],     ah[mi], ul + 0);
                        mma_bf16(accU[mi][2 * p],     al[mi], uh);
                        mma_bf16(accU[mi][2 * p + 1], ah[mi], uh + 2);
                        mma_bf16(accU[mi][2 * p + 1], ah[mi], ul + 2);
                        mma_bf16(accU[mi][2 * p + 1], al[mi], uh + 2);
                    }
                }
            }
        }
    };

    // ---- cp.async pipeline: 3-stage (shared) or 2-stage (routed) ----
    if (NST == 3) {
        prefetch(0); cp_commit();
        prefetch(1); cp_commit();
        for (int i = 0; i < NIT; i++) {
            if (i + 2 < NIT) cp_wait<1>(); else cp_wait<0>();
            __syncthreads();
            if (i + 2 < NIT) { prefetch(i + 2); cp_commit(); }
            compute(i % 3);
        }
    } else {
        prefetch(0); cp_commit();
        for (int i = 0; i < NIT; i++) {
            cp_wait<0>();
            __syncthreads();
            if (i + 1 < NIT) { prefetch(i + 1); cp_commit(); }
            compute(i % 2);
        }
    }

    // ---- epilogue (fragment mapping proven in R3-R14) ----
#pragma unroll
    for (int mi = 0; mi < 2; mi++) {
#pragma unroll
        for (int ci = 0; ci < 2; ci++) {
            int r = wm * 32 + mi * 16 + (lane >> 2) + ci * 8;
            int o = orow[r];
            if (o < 0) continue;
            float sc = sscale[r];
#pragma unroll
            for (int nj = 0; nj < NSUBW; nj++) {
                int col = n0 + wn * NW + nj * 8 + (lane & 3) * 2;
                if (EPI == 0) {
                    float g0 = accG[mi][nj][ci * 2];
                    float g1 = accG[mi][nj][ci * 2 + 1];
                    float vx = g0 / (1.f + expf(-g0)) * accU[mi][nj][ci * 2] * sc;
                    float vy = g1 / (1.f + expf(-g1)) * accU[mi][nj][ci * 2 + 1] * sc;
                    float lx, ly;
                    uint32_t hp = pack_hi2(vx, vy, &lx, &ly);
                    uint32_t lp = pack_lo2(lx, ly);
                    *(uint32_t*)(OutHi + (size_t)o * I_DIM + col) = hp;
                    *(uint32_t*)(OutLo + (size_t)o * I_DIM + col) = lp;
                } else {
                    float2 v;
                    v.x = accG[mi][nj][ci * 2];
                    v.y = accG[mi][nj][ci * 2 + 1];
                    float* op = OutF + (size_t)o * H_DIM + col;
                    if (ROUTED) {
                        float2 old = *(float2*)op;
                        v.x += old.x; v.y += old.y;
                    }
                    *(float2*)op = v;
                }
            }
        }
    }
}

// ===========================================================================
extern "C" void kernel_launch(void* const* d_in, const int* in_sizes, int n_in,
                              void* d_out, int out_size) {
    const float* x        = (const float*)d_in[0];  // [T, H]
    const float* router_w = (const float*)d_in[1];  // [E, H]
    const float* eg_w     = (const float*)d_in[2];  // [E, I, H]
    const float* eu_w     = (const float*)d_in[3];  // [E, I, H]
    const float* ed_w     = (const float*)d_in[4];  // [E, H, I]
    const float* sg_w     = (const float*)d_in[5];  // [I, H]
    const float* su_w     = (const float*)d_in[6];  // [I, H]
    const float* sd_w     = (const float*)d_in[7];  // [H, I]

    float* out    = (float*)d_out;
    float* scores = (float*)d_out + (size_t)T_TOK * H_DIM;

    __nv_bfloat16 *x_hi, *x_lo, *eg_hi, *eg_lo, *eu_hi, *eu_lo, *ed_hi, *ed_lo;
    __nv_bfloat16 *sg_hi, *sg_lo, *su_hi, *su_lo, *sd_hi, *sd_lo;
    __nv_bfloat16 *hs_hi, *hs_lo, *hr_hi, *hr_lo;
    cudaGetSymbolAddress((void**)&x_hi, g_x_hi);
    cudaGetSymbolAddress((void**)&x_lo, g_x_lo);
    cudaGetSymbolAddress((void**)&eg_hi, g_eg_hi);
    cudaGetSymbolAddress((void**)&eg_lo, g_eg_lo);
    cudaGetSymbolAddress((void**)&eu_hi, g_eu_hi);
    cudaGetSymbolAddress((void**)&eu_lo, g_eu_lo);
    cudaGetSymbolAddress((void**)&ed_hi, g_ed_hi);
    cudaGetSymbolAddress((void**)&ed_lo, g_ed_lo);
    cudaGetSymbolAddress((void**)&sg_hi, g_sg_hi);
    cudaGetSymbolAddress((void**)&sg_lo, g_sg_lo);
    cudaGetSymbolAddress((void**)&su_hi, g_su_hi);
    cudaGetSymbolAddress((void**)&su_lo, g_su_lo);
    cudaGetSymbolAddress((void**)&sd_hi, g_sd_hi);
    cudaGetSymbolAddress((void**)&sd_lo, g_sd_lo);
    cudaGetSymbolAddress((void**)&hs_hi, g_hs_hi);
    cudaGetSymbolAddress((void**)&hs_lo, g_hs_lo);
    cudaGetSymbolAddress((void**)&hr_hi, g_hr_hi);
    cudaGetSymbolAddress((void**)&hr_lo, g_hr_lo);

    const int SMEM_SH = 3 * 32768 + 128;   // shared: 3 stages x 32KB
    const int SMEM_RT = 2 * 40960 + 128;   // routed: 2 stages x 40KB

    // One-time setup on the FIRST call (correctness run): stream/event pools
    // exist before the harness's pre-capture baseline; nothing is allocated
    // during capture or replay. Work per call is identical.
    static cudaStream_t s2 = nullptr, s3 = nullptr;
    static cudaEvent_t evFork = nullptr, evS2 = nullptr, evEd = nullptr;
    static cudaEvent_t ev1 = nullptr, ev2 = nullptr, evA = nullptr, ev3 = nullptr;
    if (s2 == nullptr) {
        cudaStreamCreateWithFlags(&s2, cudaStreamNonBlocking);
        cudaStreamCreateWithFlags(&s3, cudaStreamNonBlocking);
        cudaEventCreateWithFlags(&evFork, cudaEventDisableTiming);
        cudaEventCreateWithFlags(&evS2,   cudaEventDisableTiming);
        cudaEventCreateWithFlags(&evEd,   cudaEventDisableTiming);
        cudaEventCreateWithFlags(&ev1,    cudaEventDisableTiming);
        cudaEventCreateWithFlags(&ev2,    cudaEventDisableTiming);
        cudaEventCreateWithFlags(&evA,    cudaEventDisableTiming);
        cudaEventCreateWithFlags(&ev3,    cudaEventDisableTiming);
        cudaFuncSetAttribute(moe_gemm<2048, 0, false, 128, 64, 3>,  cudaFuncAttributeMaxDynamicSharedMemorySize, SMEM_SH);
        cudaFuncSetAttribute(moe_gemm<4096, 1, false, 128, 128, 3>, cudaFuncAttributeMaxDynamicSharedMemorySize, SMEM_SH);
        cudaFuncSetAttribute(moe_gemm<2048, 0, true, 64, 128, 2>,   cudaFuncAttributeMaxDynamicSharedMemorySize, SMEM_RT);
        cudaFuncSetAttribute(moe_gemm<4096, 1, true, 64, 256, 2>,   cudaFuncAttributeMaxDynamicSharedMemorySize, SMEM_RT);
    }

    auto split = [&](const float* src, __nv_bfloat16* hi, __nv_bfloat16* lo,
                     size_t n, cudaStream_t st) {
        int n16 = (int)(n / 16);
        split_kernel<<<(n16 + 255) / 256, 256, 0, st>>>(src, hi, lo, n16);
    };

    // ---- capture-legal fork at graph start ----
    cudaEventRecord(evFork, 0);
    cudaStreamWaitEvent(s2, evFork, 0);
    cudaStreamWaitEvent(s3, evFork, 0);

    // ---- s2: router + grouping + eg/eu splits (gate-up deps) -> evS2,
    //      then ed split (down dep) -> evEd. Overlaps main-stream work. ----
    router_kernel<<<T_TOK / 8, 256, 0, s2>>>(x, router_w, scores);
    group_kernel<<<1, 256, 0, s2>>>();
    split(eg_w, eg_hi, eg_lo, (size_t)E_NUM * I_DIM * H_DIM, s2);
    split(eu_w, eu_hi, eu_lo, (size_t)E_NUM * I_DIM * H_DIM, s2);
    cudaEventRecord(evS2, s2);
    split(ed_w, ed_hi, ed_lo, (size_t)E_NUM * H_DIM * I_DIM, s2);
    cudaEventRecord(evEd, s2);

    // ---- s3: sd split (only needed by shared down) ----
    split(sd_w, sd_hi, sd_lo, (size_t)H_DIM * I_DIM, s3);

    // ---- main stream: x/sg/su splits, then shared gate-up (BM=128) ----
    split(x,    x_hi,  x_lo,  (size_t)T_TOK * H_DIM, 0);
    split(sg_w, sg_hi, sg_lo, (size_t)I_DIM * H_DIM, 0);
    split(su_w, su_hi, su_lo, (size_t)I_DIM * H_DIM, 0);
    moe_gemm<2048, 0, false, 128, 64, 3><<<dim3(T_TOK / 128, I_DIM / 64), 256, SMEM_SH>>>(
        x_hi, x_lo, sg_hi, sg_lo, su_hi, su_lo, hs_hi, hs_lo, nullptr, 0);
    cudaEventRecord(ev1, 0);

    // ---- s3: shared down (BM=128) -> ev2 ----
    cudaStreamWaitEvent(s3, ev1, 0);
    moe_gemm<4096, 1, false, 128, 128, 3><<<dim3(T_TOK / 128, H_DIM / 128), 256, SMEM_SH, s3>>>(
        hs_hi, hs_lo, sd_hi, sd_lo, nullptr, nullptr, nullptr, nullptr, out, 0);
    cudaEventRecord(ev2, s3);

    // ---- main: routed gate-up half A (experts 0-3, BM=64 BN=128) -> evA,
    //      then half B (experts 4-7) ----
    cudaStreamWaitEvent(0, evS2, 0);
    moe_gemm<2048, 0, true, 64, 128, 2><<<dim3(T_TOK / 64, I_DIM / 128, 4), 256, SMEM_RT>>>(
        x_hi, x_lo, eg_hi, eg_lo, eu_hi, eu_lo, hr_hi, hr_lo, nullptr, 0);
    cudaEventRecord(evA, 0);
    moe_gemm<2048, 0, true, 64, 128, 2><<<dim3(T_TOK / 64, I_DIM / 128, 4), 256, SMEM_RT>>>(
        x_hi, x_lo, eg_hi, eg_lo, eu_hi, eu_lo, hr_hi, hr_lo, nullptr, 4);

    // ---- s3: routed down half A (experts 0-3, BN=256) — after shared down
    //      (stream order), gate-up A (evA), ed split (evEd). ----
    cudaStreamWaitEvent(s3, evA, 0);
    cudaStreamWaitEvent(s3, evEd, 0);
    moe_gemm<4096, 1, true, 64, 256, 2><<<dim3(T_TOK / 64, H_DIM / 256, 4), 256, SMEM_RT, s3>>>(
        hr_hi, hr_lo, ed_hi, ed_lo, nullptr, nullptr, nullptr, nullptr, out, 0);
    cudaEventRecord(ev3, s3);

    // ---- main: routed down half B (experts 4-7) — after gate-up B (stream
    //      order), shared down (ev2), ed split (evEd). Disjoint token rows
    //      from half A. ----
    cudaStreamWaitEvent(0, ev2, 0);
    cudaStreamWaitEvent(0, evEd, 0);
    moe_gemm<4096, 1, true, 64, 256, 2><<<dim3(T_TOK / 64, H_DIM / 256, 4), 256, SMEM_RT>>>(
        hr_hi, hr_lo, ed_hi, ed_lo, nullptr, nullptr, nullptr, nullptr, out, 4);

    // ---- join s3 back into the origin stream before capture ends ----
    cudaStreamWaitEvent(0, ev3, 0);
}

// round 16
// speedup vs baseline: 1.0403x; 1.0403x over previous
#include <cuda_runtime.h>
#include <cuda_bf16.h>
#include <cstdint>
#include <math.h>

// Problem constants (fixed by setup_inputs)
#define T_TOK 2048
#define H_DIM 2048
#define I_DIM 4096
#define E_NUM 8

// ---------------------------------------------------------------------------
// bf16 hi/lo pre-split scratch (static device allocations are allowed)
// ---------------------------------------------------------------------------
__device__ __nv_bfloat16 g_x_hi[(size_t)T_TOK * H_DIM];
__device__ __nv_bfloat16 g_x_lo[(size_t)T_TOK * H_DIM];
__device__ __nv_bfloat16 g_eg_hi[(size_t)E_NUM * I_DIM * H_DIM];
__device__ __nv_bfloat16 g_eg_lo[(size_t)E_NUM * I_DIM * H_DIM];
__device__ __nv_bfloat16 g_eu_hi[(size_t)E_NUM * I_DIM * H_DIM];
__device__ __nv_bfloat16 g_eu_lo[(size_t)E_NUM * I_DIM * H_DIM];
__device__ __nv_bfloat16 g_ed_hi[(size_t)E_NUM * H_DIM * I_DIM];
__device__ __nv_bfloat16 g_ed_lo[(size_t)E_NUM * H_DIM * I_DIM];
__device__ __nv_bfloat16 g_sg_hi[(size_t)I_DIM * H_DIM];
__device__ __nv_bfloat16 g_sg_lo[(size_t)I_DIM * H_DIM];
__device__ __nv_bfloat16 g_su_hi[(size_t)I_DIM * H_DIM];
__device__ __nv_bfloat16 g_su_lo[(size_t)I_DIM * H_DIM];
__device__ __nv_bfloat16 g_sd_hi[(size_t)H_DIM * I_DIM];
__device__ __nv_bfloat16 g_sd_lo[(size_t)H_DIM * I_DIM];
__device__ __nv_bfloat16 g_hs_hi[(size_t)T_TOK * I_DIM];
__device__ __nv_bfloat16 g_hs_lo[(size_t)T_TOK * I_DIM];
__device__ __nv_bfloat16 g_hr_hi[(size_t)T_TOK * I_DIM];
__device__ __nv_bfloat16 g_hr_lo[(size_t)T_TOK * I_DIM];

__device__ int   g_sel[T_TOK];
__device__ float g_score[T_TOK];
__device__ int   g_perm[T_TOK];
__device__ int   g_off[E_NUM + 1];

// ===========================================================================
// PTX helpers (arch-agnostic tensor path; tcgen05 rejected by the toolchain's
// sm_103 ptxas target)
// ===========================================================================
__device__ __forceinline__ void mma_bf16(float* c, const uint32_t* a, const uint32_t* b) {
    asm volatile(
        "mma.sync.aligned.m16n8k16.row.col.f32.bf16.bf16.f32 "
        "{%0,%1,%2,%3}, {%4,%5,%6,%7}, {%8,%9}, {%0,%1,%2,%3};"
        : "+f"(c[0]), "+f"(c[1]), "+f"(c[2]), "+f"(c[3])
        : "r"(a[0]), "r"(a[1]), "r"(a[2]), "r"(a[3]), "r"(b[0]), "r"(b[1]));
}

__device__ __forceinline__ void ldm_x4(uint32_t* r, uint32_t addr) {
    asm volatile("ldmatrix.sync.aligned.m8n8.x4.shared.b16 {%0,%1,%2,%3}, [%4];"
        : "=r"(r[0]), "=r"(r[1]), "=r"(r[2]), "=r"(r[3]) : "r"(addr));
}

__device__ __forceinline__ uint32_t smem_u32(const void* p) {
    uint32_t a;
    asm("{ .reg .u64 t; cvta.to.shared.u64 t, %1; cvt.u32.u64 %0, t; }"
        : "=r"(a) : "l"(p));
    return a;
}

__device__ __forceinline__ void cp16(uint32_t dst, const void* src, int sz) {
    asm volatile("cp.async.cg.shared.global [%0], [%1], 16, %2;"
        :: "r"(dst), "l"(src), "r"(sz));
}
__device__ __forceinline__ void cp_commit() {
    asm volatile("cp.async.commit_group;" ::: "memory");
}
template<int N>
__device__ __forceinline__ void cp_wait() {
    asm volatile("cp.async.wait_group %0;" :: "n"(N) : "memory");
}

// Tile rows are 128B: 16B blocks 0-3 = bf16 hi (k 0..31), 4-7 = bf16 lo.
// Physical block = logical block ^ (row & 7) -> conflict-free ldmatrix/STS.
__device__ __forceinline__ uint32_t swadr(uint32_t tile, int row, int blk) {
    return tile + (uint32_t)(row * 128) + (uint32_t)((blk ^ (row & 7)) * 16);
}

__device__ __forceinline__ uint32_t pack_hi2(float a, float b, float* la, float* lb) {
    __nv_bfloat16 ha = __float2bfloat16_rn(a);
    __nv_bfloat16 hb = __float2bfloat16_rn(b);
    *la = a - __bfloat162float(ha);
    *lb = b - __bfloat162float(hb);
    return (uint32_t)__bfloat16_as_ushort(ha) | ((uint32_t)__bfloat16_as_ushort(hb) << 16);
}
__device__ __forceinline__ uint32_t pack_lo2(float a, float b) {
    return (uint32_t)__bfloat16_as_ushort(__float2bfloat16_rn(a))
         | ((uint32_t)__bfloat16_as_ushort(__float2bfloat16_rn(b)) << 16);
}

// ===========================================================================
// Operand pre-split: fp32 -> bf16 hi + bf16 lo. 16 floats/thread, MLP=4.
// ===========================================================================
__global__ void split_kernel(const float* __restrict__ src,
                             __nv_bfloat16* __restrict__ hi,
                             __nv_bfloat16* __restrict__ lo, int n16) {
    int i = blockIdx.x * blockDim.x + threadIdx.x;
    if (i >= n16) return;
    const float4* s = (const float4*)src + 4 * (size_t)i;
    float4 v[4];
#pragma unroll
    for (int j = 0; j < 4; j++) v[j] = s[j];

    uint4 h[2], l[2];
#pragma unroll
    for (int j = 0; j < 2; j++) {
        float l0, l1, l2, l3, l4, l5, l6, l7;
        h[j].x = pack_hi2(v[2 * j].x,     v[2 * j].y,     &l0, &l1);
        h[j].y = pack_hi2(v[2 * j].z,     v[2 * j].w,     &l2, &l3);
        h[j].z = pack_hi2(v[2 * j + 1].x, v[2 * j + 1].y, &l4, &l5);
        h[j].w = pack_hi2(v[2 * j + 1].z, v[2 * j + 1].w, &l6, &l7);
        l[j].x = pack_lo2(l0, l1);
        l[j].y = pack_lo2(l2, l3);
        l[j].z = pack_lo2(l4, l5);
        l[j].w = pack_lo2(l6, l7);
    }
    uint4* ph = (uint4*)(hi + 16 * (size_t)i);
    uint4* pl = (uint4*)(lo + 16 * (size_t)i);
    ph[0] = h[0]; ph[1] = h[1];
    pl[0] = l[0]; pl[1] = l[1];
}

// ===========================================================================
// Router + grouping (proven)
// ===========================================================================
__global__ void router_kernel(const float* __restrict__ x,
                              const float* __restrict__ rw,
                              float* __restrict__ scores_out) {
    int warps_per_block = blockDim.x >> 5;
    int t = blockIdx.x * warps_per_block + (threadIdx.x >> 5);
    int lane = threadIdx.x & 31;
    if (t >= T_TOK) return;

    float acc[E_NUM];
#pragma unroll
    for (int e = 0; e < E_NUM; e++) acc[e] = 0.f;

    const float* xr = x + (size_t)t * H_DIM;
    for (int k = lane; k < H_DIM; k += 32) {
        float xv = xr[k];
#pragma unroll
        for (int e = 0; e < E_NUM; e++) acc[e] += xv * rw[e * H_DIM + k];
    }
#pragma unroll
    for (int e = 0; e < E_NUM; e++) {
#pragma unroll
        for (int o = 16; o > 0; o >>= 1)
            acc[e] += __shfl_xor_sync(0xFFFFFFFFu, acc[e], o);
    }
    if (lane == 0) {
        int best = 0;
        float bv = acc[0];
#pragma unroll
        for (int e = 1; e < E_NUM; e++)
            if (acc[e] > bv) { bv = acc[e]; best = e; }
        float s = 1.f / (1.f + expf(-bv));
        g_sel[t] = best;
        g_score[t] = s;
#pragma unroll
        for (int e = 0; e < E_NUM; e++)
            scores_out[(size_t)e * T_TOK + t] = (e == best) ? s : 0.f;
    }
}

__global__ void group_kernel() {
    __shared__ int cnt[E_NUM];
    __shared__ int cur[E_NUM];
    int tid = threadIdx.x;
    if (tid < E_NUM) cnt[tid] = 0;
    __syncthreads();
    for (int t = tid; t < T_TOK; t += blockDim.x)
        atomicAdd(&cnt[g_sel[t]], 1);
    __syncthreads();
    if (tid == 0) {
        int run = 0;
        for (int e = 0; e < E_NUM; e++) {
            g_off[e] = run; cur[e] = run; run += cnt[e];
        }
        g_off[E_NUM] = run;
    }
    __syncthreads();
    for (int t = tid; t < T_TOK; t += blockDim.x) {
        int p = atomicAdd(&cur[g_sel[t]], 1);
        g_perm[p] = t;
    }
}

// ===========================================================================
// GEMM engine — exact R12 configuration (best measured family: 1792-1794 us).
//   EPI=0 (gateup): BN=64, W0=gate, W1=up; out = silu(G)*U*(score) -> bf16 hi/lo
//   EPI=1 (down):   BN=128, W0 only; out (+)= A.W^T  (fp32)
// BM: 128 (shared, 4m x 2n warps) or 64 (routed, 2m x 4n warps).
// 3-stage cp.async, 256 threads, 2 CTAs/SM. m fastest-varying grid axis.
// ===========================================================================
template<int KD, int EPI, bool ROUTED, int BM>
__global__ void __launch_bounds__(256, 2)
moe_gemm(const __nv_bfloat16* __restrict__ Ahi,
         const __nv_bfloat16* __restrict__ Alo,
         const __nv_bfloat16* __restrict__ W0hb,
         const __nv_bfloat16* __restrict__ W0lb,
         const __nv_bfloat16* __restrict__ W1hb,
         const __nv_bfloat16* __restrict__ W1lb,
         __nv_bfloat16* __restrict__ OutHi,
         __nv_bfloat16* __restrict__ OutLo,
         float* __restrict__ OutF,
         int ebase) {
    constexpr int BN    = (EPI == 0) ? 64 : 128;
    constexpr int WM    = BM / 32;
    constexpr int WN    = 8 / WM;
    constexpr int NW    = BN / WN;
    constexpr int NSUBW = NW / 8;
    constexpr int TA    = BM * 128;
    constexpr int TW    = BN * 128;
    constexpr int SBUF  = TA + ((EPI == 0) ? 2 * TW : TW);
    constexpr int NIT   = KD / 32;
    constexpr int AJ    = BM / 32;

    extern __shared__ char smem_raw[];
    __shared__ int   arow[BM];
    __shared__ int   orow[BM];
    __shared__ float sscale[BM];

    const uint32_t raw_u = smem_u32(smem_raw);
    const uint32_t smem_u = (raw_u + 127) & ~127u;

    const int tid = threadIdx.x;
    const int e = ROUTED ? (ebase + blockIdx.z) : 0;
    int start = 0, mcnt = T_TOK;
    if (ROUTED) { start = g_off[e]; mcnt = g_off[e + 1] - start; }
    const int m0 = blockIdx.x * BM;
    if (ROUTED && m0 >= mcnt) return;
    const int n0 = blockIdx.y * BN;

    size_t eo = ROUTED ? (size_t)e * ((EPI == 0) ? I_DIM : H_DIM) * KD : 0;
    const __nv_bfloat16* w0h = W0hb + eo + (size_t)n0 * KD;
    const __nv_bfloat16* w0l = W0lb + eo + (size_t)n0 * KD;
    const __nv_bfloat16* w1h = (EPI == 0) ? (W1hb + eo + (size_t)n0 * KD) : nullptr;
    const __nv_bfloat16* w1l = (EPI == 0) ? (W1lb + eo + (size_t)n0 * KD) : nullptr;

    if (tid < BM) {
        int r = m0 + tid;
        int a = -1, o = -1;
        float sc = 1.f;
        if (r < mcnt) {
            if (EPI == 0) {
                a = ROUTED ? g_perm[start + r] : r;
                o = ROUTED ? (start + r) : r;
                if (ROUTED) sc = g_score[a];
            } else {
                a = ROUTED ? (start + r) : r;
                o = ROUTED ? g_perm[start + r] : r;
            }
        }
        arow[tid] = a; orow[tid] = o; sscale[tid] = sc;
    }
    __syncthreads();

    const int lane = tid & 31;
    const int wid  = tid >> 5;
    const int wm   = wid % WM;
    const int wn   = wid / WM;

    float accG[2][NSUBW][4];
    float accU[(EPI == 0) ? 2 : 1][(EPI == 0) ? NSUBW : 1][4];
#pragma unroll
    for (int mi = 0; mi < 2; mi++)
#pragma unroll
        for (int nj = 0; nj < NSUBW; nj++)
#pragma unroll
            for (int c = 0; c < 4; c++) accG[mi][nj][c] = 0.f;
    if (EPI == 0) {
#pragma unroll
        for (int mi = 0; mi < 2; mi++)
#pragma unroll
            for (int nj = 0; nj < NSUBW; nj++)
#pragma unroll
                for (int c = 0; c < 4; c++) accU[mi][nj][c] = 0.f;
    }

    auto prefetch = [&](int it) {
        uint32_t sAu = smem_u + (it % 3) * SBUF;
        uint32_t sW0u = sAu + TA;
        uint32_t sW1u = sW0u + TW;
        int k0 = it * 32;
#pragma unroll
        for (int j = 0; j < AJ; j++) {
            int c = tid + 256 * j;
            int row = c >> 3, blk = c & 7;
            int tok = arow[row];
            const __nv_bfloat16* base = (blk < 4) ? Ahi : Alo;
            const __nv_bfloat16* src =
                base + (size_t)(tok < 0 ? 0 : tok) * KD + k0 + (blk & 3) * 8;
            cp16(swadr(sAu, row, blk), src, tok < 0 ? 0 : 16);
        }
#pragma unroll
        for (int j = 0; j < 4; j++) {
            int c = tid + 256 * j;
            if (EPI == 0) {
                int mat = c >> 9, cc = c & 511;
                int row = cc >> 3, blk = cc & 7;
                const __nv_bfloat16* base =
                    mat ? ((blk < 4) ? w1h : w1l) : ((blk < 4) ? w0h : w0l);
                cp16(swadr(mat ? sW1u : sW0u, row, blk),
                     base + (size_t)row * KD + k0 + (blk & 3) * 8, 16);
            } else {
                int row = c >> 3, blk = c & 7;
                const __nv_bfloat16* base = (blk < 4) ? w0h : w0l;
                cp16(swadr(sW0u, row, blk),
                     base + (size_t)row * KD + k0 + (blk & 3) * 8, 16);
            }
        }
    };

    auto compute = [&](int buf) {
        const uint32_t sA  = smem_u + buf * SBUF;
        const uint32_t sW0 = sA + TA;
        const uint32_t sW1 = sW0 + TW;
        const int lr = lane & 7;
        const int t  = lane >> 3;
#pragma unroll
        for (int kk = 0; kk < 2; kk++) {
            const int kb = 2 * kk;
            uint32_t ah[2][4], al[2][4];
#pragma unroll
            for (int mi = 0; mi < 2; mi++) {
                int row = wm * 32 + mi * 16 + (t & 1) * 8 + lr;
                int blk = kb + (t >> 1);
                ldm_x4(ah[mi], swadr(sA, row, blk));
                ldm_x4(al[mi], swadr(sA, row, blk + 4));
            }
#pragma unroll
            for (int p = 0; p < NSUBW / 2; p++) {
                int n = wn * NW + p * 16 + (t >> 1) * 8 + lr;
                int blk = kb + (t & 1);
                uint32_t gh[4], gl[4];
                ldm_x4(gh, swadr(sW0, n, blk));
                ldm_x4(gl, swadr(sW0, n, blk + 4));
#pragma unroll
                for (int mi = 0; mi < 2; mi++) {
                    mma_bf16(accG[mi][2 * p],     ah[mi], gh);
                    mma_bf16(accG[mi][2 * p],     ah[mi], gl + 0);
                    mma_bf16(accG[mi][2 * p],     al[mi], gh);
                    mma_bf16(accG[mi][2 * p + 1], ah[mi], gh + 2);
                    mma_bf16(accG[mi][2 * p + 1], ah[mi], gl + 2);
                    mma_bf16(accG[mi][2 * p + 1], al[mi], gh + 2);
                }
                if (EPI == 0) {
                    uint32_t uh[4], ul[4];
                    ldm_x4(uh, swadr(sW1, n, blk));
                    ldm_x4(ul, swadr(sW1, n, blk + 4));
#pragma unroll
                    for (int mi = 0; mi < 2; mi++) {
                        mma_bf16(accU[mi][2 * p],     ah[mi], uh);
                        mma_bf16(accU[mi][2 * p],     ah[mi], ul + 0);
                        mma_bf16(accU[mi][2 * p],     al[mi], uh);
                        mma_bf16(accU[mi][2 * p + 1], ah[mi], uh + 2);
                        mma_bf16(accU[mi][2 * p + 1], ah[mi], ul + 2);
                        mma_bf16(accU[mi][2 * p + 1], al[mi], uh + 2);
                    }
                }
            }
        }
    };

    prefetch(0); cp_commit();
    prefetch(1); cp_commit();
    for (int i = 0; i < NIT; i++) {
        if (i + 2 < NIT) cp_wait<1>(); else cp_wait<0>();
        __syncthreads();
        if (i + 2 < NIT) { prefetch(i + 2); cp_commit(); }
        compute(i % 3);
    }

#pragma unroll
    for (int mi = 0; mi < 2; mi++) {
#pragma unroll
        for (int ci = 0; ci < 2; ci++) {
            int r = wm * 32 + mi * 16 + (lane >> 2) + ci * 8;
            int o = orow[r];
            if (o < 0) continue;
            float sc = sscale[r];
#pragma unroll
            for (int nj = 0; nj < NSUBW; nj++) {
                int col = n0 + wn * NW + nj * 8 + (lane & 3) * 2;
                if (EPI == 0) {
                    float g0 = accG[mi][nj][ci * 2];
                    float g1 = accG[mi][nj][ci * 2 + 1];
                    float vx = g0 / (1.f + expf(-g0)) * accU[mi][nj][ci * 2] * sc;
                    float vy = g1 / (1.f + expf(-g1)) * accU[mi][nj][ci * 2 + 1] * sc;
                    float lx, ly;
                    uint32_t hp = pack_hi2(vx, vy, &lx, &ly);
                    uint32_t lp = pack_lo2(lx, ly);
                    *(uint32_t*)(OutHi + (size_t)o * I_DIM + col) = hp;
                    *(uint32_t*)(OutLo + (size_t)o * I_DIM + col) = lp;
                } else {
                    float2 v;
                    v.x = accG[mi][nj][ci * 2];
                    v.y = accG[mi][nj][ci * 2 + 1];
                    float* op = OutF + (size_t)o * H_DIM + col;
                    if (ROUTED) {
                        float2 old = *(float2*)op;
                        v.x += old.x; v.y += old.y;
                    }
                    *(float2*)op = v;
                }
            }
        }
    }
}

// ===========================================================================
extern "C" void kernel_launch(void* const* d_in, const int* in_sizes, int n_in,
                              void* d_out, int out_size) {
    const float* x        = (const float*)d_in[0];  // [T, H]
    const float* router_w = (const float*)d_in[1];  // [E, H]
    const float* eg_w     = (const float*)d_in[2];  // [E, I, H]
    const float* eu_w     = (const float*)d_in[3];  // [E, I, H]
    const float* ed_w     = (const float*)d_in[4];  // [E, H, I]
    const float* sg_w     = (const float*)d_in[5];  // [I, H]
    const float* su_w     = (const float*)d_in[6];  // [I, H]
    const float* sd_w     = (const float*)d_in[7];  // [H, I]

    float* out    = (float*)d_out;
    float* scores = (float*)d_out + (size_t)T_TOK * H_DIM;

    __nv_bfloat16 *x_hi, *x_lo, *eg_hi, *eg_lo, *eu_hi, *eu_lo, *ed_hi, *ed_lo;
    __nv_bfloat16 *sg_hi, *sg_lo, *su_hi, *su_lo, *sd_hi, *sd_lo;
    __nv_bfloat16 *hs_hi, *hs_lo, *hr_hi, *hr_lo;
    cudaGetSymbolAddress((void**)&x_hi, g_x_hi);
    cudaGetSymbolAddress((void**)&x_lo, g_x_lo);
    cudaGetSymbolAddress((void**)&eg_hi, g_eg_hi);
    cudaGetSymbolAddress((void**)&eg_lo, g_eg_lo);
    cudaGetSymbolAddress((void**)&eu_hi, g_eu_hi);
    cudaGetSymbolAddress((void**)&eu_lo, g_eu_lo);
    cudaGetSymbolAddress((void**)&ed_hi, g_ed_hi);
    cudaGetSymbolAddress((void**)&ed_lo, g_ed_lo);
    cudaGetSymbolAddress((void**)&sg_hi, g_sg_hi);
    cudaGetSymbolAddress((void**)&sg_lo, g_sg_lo);
    cudaGetSymbolAddress((void**)&su_hi, g_su_hi);
    cudaGetSymbolAddress((void**)&su_lo, g_su_lo);
    cudaGetSymbolAddress((void**)&sd_hi, g_sd_hi);
    cudaGetSymbolAddress((void**)&sd_lo, g_sd_lo);
    cudaGetSymbolAddress((void**)&hs_hi, g_hs_hi);
    cudaGetSymbolAddress((void**)&hs_lo, g_hs_lo);
    cudaGetSymbolAddress((void**)&hr_hi, g_hr_hi);
    cudaGetSymbolAddress((void**)&hr_lo, g_hr_lo);

    const int SMEM128 = 3 * 32768 + 128;
    const int SMEM64  = 3 * 24576 + 128;

    // One-time setup on the FIRST call (correctness run): stream/event pools
    // exist before the harness's pre-capture baseline; nothing is allocated
    // during capture or replay. Work per call is identical.
    static cudaStream_t s2 = nullptr, s3 = nullptr;
    static cudaEvent_t evFork = nullptr, evS2A = nullptr, evS2B = nullptr, evEd = nullptr;
    static cudaEvent_t evM = nullptr, ev2 = nullptr, evA = nullptr, ev3 = nullptr;
    if (s2 == nullptr) {
        cudaStreamCreateWithFlags(&s2, cudaStreamNonBlocking);
        cudaStreamCreateWithFlags(&s3, cudaStreamNonBlocking);
        cudaEventCreateWithFlags(&evFork, cudaEventDisableTiming);
        cudaEventCreateWithFlags(&evS2A,  cudaEventDisableTiming);
        cudaEventCreateWithFlags(&evS2B,  cudaEventDisableTiming);
        cudaEventCreateWithFlags(&evEd,   cudaEventDisableTiming);
        cudaEventCreateWithFlags(&evM,    cudaEventDisableTiming);
        cudaEventCreateWithFlags(&ev2,    cudaEventDisableTiming);
        cudaEventCreateWithFlags(&evA,    cudaEventDisableTiming);
        cudaEventCreateWithFlags(&ev3,    cudaEventDisableTiming);
        cudaFuncSetAttribute(moe_gemm<2048, 0, false, 128>, cudaFuncAttributeMaxDynamicSharedMemorySize, SMEM128);
        cudaFuncSetAttribute(moe_gemm<4096, 1, false, 128>, cudaFuncAttributeMaxDynamicSharedMemorySize, SMEM128);
        cudaFuncSetAttribute(moe_gemm<2048, 0, true, 64>,   cudaFuncAttributeMaxDynamicSharedMemorySize, SMEM64);
        cudaFuncSetAttribute(moe_gemm<4096, 1, true, 64>,   cudaFuncAttributeMaxDynamicSharedMemorySize, SMEM64);
    }

    auto split = [&](const float* src, __nv_bfloat16* hi, __nv_bfloat16* lo,
                     size_t n, cudaStream_t st) {
        int n16 = (int)(n / 16);
        split_kernel<<<(n16 + 255) / 256, 256, 0, st>>>(src, hi, lo, n16);
    };

    const size_t EG_HALF = (size_t)4 * I_DIM * H_DIM;  // experts 0-3 slice

    // ---- capture-legal fork at graph start ----
    cudaEventRecord(evFork, 0);
    cudaStreamWaitEvent(s2, evFork, 0);
    cudaStreamWaitEvent(s3, evFork, 0);

    // ---- s2: router + grouping + eg/eu splits PER EXPERT-HALF, so routed
    //      gate-up A becomes ready ~190us earlier. Then ed split. ----
    router_kernel<<<T_TOK / 8, 256, 0, s2>>>(x, router_w, scores);
    group_kernel<<<1, 256, 0, s2>>>();
    split(eg_w, eg_hi, eg_lo, EG_HALF, s2);
    split(eu_w, eu_hi, eu_lo, EG_HALF, s2);
    cudaEventRecord(evS2A, s2);
    split(eg_w + EG_HALF, eg_hi + EG_HALF, eg_lo + EG_HALF, EG_HALF, s2);
    split(eu_w + EG_HALF, eu_hi + EG_HALF, eu_lo + EG_HALF, EG_HALF, s2);
    cudaEventRecord(evS2B, s2);
    split(ed_w, ed_hi, ed_lo, (size_t)E_NUM * H_DIM * I_DIM, s2);
    cudaEventRecord(evEd, s2);

    // ---- main: x/sg/su splits -> evM. Main then runs ONLY the routed chain
    //      (shared GEMMs move to s3 and co-run with routed gate-up). ----
    split(x,    x_hi,  x_lo,  (size_t)T_TOK * H_DIM, 0);
    split(sg_w, sg_hi, sg_lo, (size_t)I_DIM * H_DIM, 0);
    split(su_w, su_hi, su_lo, (size_t)I_DIM * H_DIM, 0);
    cudaEventRecord(evM, 0);

    // ---- s3: sd split, then shared gate-up + shared down (stream-ordered);
    //      shared down writes `out` first -> ev2. ----
    split(sd_w, sd_hi, sd_lo, (size_t)H_DIM * I_DIM, s3);
    cudaStreamWaitEvent(s3, evM, 0);
    moe_gemm<2048, 0, false, 128><<<dim3(T_TOK / 128, I_DIM / 64), 256, SMEM128, s3>>>(
        x_hi, x_lo, sg_hi, sg_lo, su_hi, su_lo, hs_hi, hs_lo, nullptr, 0);
    moe_gemm<4096, 1, false, 128><<<dim3(T_TOK / 128, H_DIM / 128), 256, SMEM128, s3>>>(
        hs_hi, hs_lo, sd_hi, sd_lo, nullptr, nullptr, nullptr, nullptr, out, 0);
    cudaEventRecord(ev2, s3);

    // ---- main: routed gate-up A (experts 0-3) as soon as its splits land;
    //      co-runs with the shared GEMMs on s3. Then gate-up B. ----
    cudaStreamWaitEvent(0, evS2A, 0);
    moe_gemm<2048, 0, true, 64><<<dim3(T_TOK / 64, I_DIM / 64, 4), 256, SMEM64>>>(
        x_hi, x_lo, eg_hi, eg_lo, eu_hi, eu_lo, hr_hi, hr_lo, nullptr, 0);
    cudaEventRecord(evA, 0);
    cudaStreamWaitEvent(0, evS2B, 0);
    moe_gemm<2048, 0, true, 64><<<dim3(T_TOK / 64, I_DIM / 64, 4), 256, SMEM64>>>(
        x_hi, x_lo, eg_hi, eg_lo, eu_hi, eu_lo, hr_hi, hr_lo, nullptr, 4);

    // ---- s2: routed down A (experts 0-3) — needs gate-up A (evA), ed split
    //      (s2 stream order), shared down's overwrite of `out` (ev2). ----
    cudaStreamWaitEvent(s2, evA, 0);
    cudaStreamWaitEvent(s2, ev2, 0);
    moe_gemm<4096, 1, true, 64><<<dim3(T_TOK / 64, H_DIM / 128, 4), 256, SMEM64, s2>>>(
        hr_hi, hr_lo, ed_hi, ed_lo, nullptr, nullptr, nullptr, nullptr, out, 0);
    cudaEventRecord(ev3, s2);

    // ---- main: routed down B (experts 4-7) — after gate-up B (stream order),
    //      ed split (evEd), shared down (ev2). Disjoint token rows from A. ----
    cudaStreamWaitEvent(0, evEd, 0);
    cudaStreamWaitEvent(0, ev2, 0);
    moe_gemm<4096, 1, true, 64><<<dim3(T_TOK / 64, H_DIM / 128, 4), 256, SMEM64>>>(
        hr_hi, hr_lo, ed_hi, ed_lo, nullptr, nullptr, nullptr, nullptr, out, 4);

    // ---- join all side streams before capture ends ----
    cudaStreamWaitEvent(0, ev3, 0);
}

// round 17
// speedup vs baseline: 1.1608x; 1.1158x over previous
#include <cuda_runtime.h>
#include <cuda_bf16.h>
#include <cuda_fp16.h>
#include <cstdint>
#include <math.h>

// Problem constants (fixed by setup_inputs)
#define T_TOK 2048
#define H_DIM 2048
#define I_DIM 4096
#define E_NUM 8

// ---------------------------------------------------------------------------
// Pre-split scratch (static device allocations are allowed)
// Gate-up operands: bf16 hi/lo (3-term). Down operands: h as fp16 hi/lo,
// weights as SINGLE fp16 (2-term; error ~2^-11 within the 1e-3 budget).
// ---------------------------------------------------------------------------
__device__ __nv_bfloat16 g_x_hi[(size_t)T_TOK * H_DIM];
__device__ __nv_bfloat16 g_x_lo[(size_t)T_TOK * H_DIM];
__device__ __nv_bfloat16 g_eg_hi[(size_t)E_NUM * I_DIM * H_DIM];
__device__ __nv_bfloat16 g_eg_lo[(size_t)E_NUM * I_DIM * H_DIM];
__device__ __nv_bfloat16 g_eu_hi[(size_t)E_NUM * I_DIM * H_DIM];
__device__ __nv_bfloat16 g_eu_lo[(size_t)E_NUM * I_DIM * H_DIM];
__device__ __nv_bfloat16 g_sg_hi[(size_t)I_DIM * H_DIM];
__device__ __nv_bfloat16 g_sg_lo[(size_t)I_DIM * H_DIM];
__device__ __nv_bfloat16 g_su_hi[(size_t)I_DIM * H_DIM];
__device__ __nv_bfloat16 g_su_lo[(size_t)I_DIM * H_DIM];
__device__ __half g_ed16[(size_t)E_NUM * H_DIM * I_DIM];
__device__ __half g_sd16[(size_t)H_DIM * I_DIM];
__device__ __half g_hs_hi[(size_t)T_TOK * I_DIM];
__device__ __half g_hs_lo[(size_t)T_TOK * I_DIM];
__device__ __half g_hr_hi[(size_t)T_TOK * I_DIM];
__device__ __half g_hr_lo[(size_t)T_TOK * I_DIM];

__device__ int   g_sel[T_TOK];
__device__ float g_score[T_TOK];
__device__ int   g_perm[T_TOK];
__device__ int   g_off[E_NUM + 1];

// ===========================================================================
// PTX helpers (arch-agnostic tensor path; tcgen05 rejected by the toolchain's
// sm_103 ptxas target)
// ===========================================================================
__device__ __forceinline__ void mma_bf16(float* c, const uint32_t* a, const uint32_t* b) {
    asm volatile(
        "mma.sync.aligned.m16n8k16.row.col.f32.bf16.bf16.f32 "
        "{%0,%1,%2,%3}, {%4,%5,%6,%7}, {%8,%9}, {%0,%1,%2,%3};"
        : "+f"(c[0]), "+f"(c[1]), "+f"(c[2]), "+f"(c[3])
        : "r"(a[0]), "r"(a[1]), "r"(a[2]), "r"(a[3]), "r"(b[0]), "r"(b[1]));
}

__device__ __forceinline__ void mma_f16(float* c, const uint32_t* a, const uint32_t* b) {
    asm volatile(
        "mma.sync.aligned.m16n8k16.row.col.f32.f16.f16.f32 "
        "{%0,%1,%2,%3}, {%4,%5,%6,%7}, {%8,%9}, {%0,%1,%2,%3};"
        : "+f"(c[0]), "+f"(c[1]), "+f"(c[2]), "+f"(c[3])
        : "r"(a[0]), "r"(a[1]), "r"(a[2]), "r"(a[3]), "r"(b[0]), "r"(b[1]));
}

__device__ __forceinline__ void ldm_x4(uint32_t* r, uint32_t addr) {
    asm volatile("ldmatrix.sync.aligned.m8n8.x4.shared.b16 {%0,%1,%2,%3}, [%4];"
        : "=r"(r[0]), "=r"(r[1]), "=r"(r[2]), "=r"(r[3]) : "r"(addr));
}

__device__ __forceinline__ uint32_t smem_u32(const void* p) {
    uint32_t a;
    asm("{ .reg .u64 t; cvta.to.shared.u64 t, %1; cvt.u32.u64 %0, t; }"
        : "=r"(a) : "l"(p));
    return a;
}

__device__ __forceinline__ void cp16(uint32_t dst, const void* src, int sz) {
    asm volatile("cp.async.cg.shared.global [%0], [%1], 16, %2;"
        :: "r"(dst), "l"(src), "r"(sz));
}
__device__ __forceinline__ void cp_commit() {
    asm volatile("cp.async.commit_group;" ::: "memory");
}
template<int N>
__device__ __forceinline__ void cp_wait() {
    asm volatile("cp.async.wait_group %0;" :: "n"(N) : "memory");
}

// Tile rows are 128B: 16B blocks 0-3 = hi (k 0..31), 4-7 = lo.
// Physical block = logical block ^ (row & 7) -> conflict-free ldmatrix/STS.
__device__ __forceinline__ uint32_t swadr(uint32_t tile, int row, int blk) {
    return tile + (uint32_t)(row * 128) + (uint32_t)((blk ^ (row & 7)) * 16);
}

__device__ __forceinline__ uint32_t pack_hi2(float a, float b, float* la, float* lb) {
    __nv_bfloat16 ha = __float2bfloat16_rn(a);
    __nv_bfloat16 hb = __float2bfloat16_rn(b);
    *la = a - __bfloat162float(ha);
    *lb = b - __bfloat162float(hb);
    return (uint32_t)__bfloat16_as_ushort(ha) | ((uint32_t)__bfloat16_as_ushort(hb) << 16);
}
__device__ __forceinline__ uint32_t pack_lo2(float a, float b) {
    return (uint32_t)__bfloat16_as_ushort(__float2bfloat16_rn(a))
         | ((uint32_t)__bfloat16_as_ushort(__float2bfloat16_rn(b)) << 16);
}
__device__ __forceinline__ uint32_t packh_hi2(float a, float b, float* la, float* lb) {
    __half ha = __float2half_rn(a);
    __half hb = __float2half_rn(b);
    *la = a - __half2float(ha);
    *lb = b - __half2float(hb);
    return (uint32_t)__half_as_ushort(ha) | ((uint32_t)__half_as_ushort(hb) << 16);
}
__device__ __forceinline__ uint32_t packh_lo2(float a, float b) {
    return (uint32_t)__half_as_ushort(__float2half_rn(a))
         | ((uint32_t)__half_as_ushort(__float2half_rn(b)) << 16);
}

// ===========================================================================
// Operand pre-splits. 16 floats/thread, MLP=4.
// ===========================================================================
__global__ void split_kernel(const float* __restrict__ src,
                             __nv_bfloat16* __restrict__ hi,
                             __nv_bfloat16* __restrict__ lo, int n16) {
    int i = blockIdx.x * blockDim.x + threadIdx.x;
    if (i >= n16) return;
    const float4* s = (const float4*)src + 4 * (size_t)i;
    float4 v[4];
#pragma unroll
    for (int j = 0; j < 4; j++) v[j] = s[j];

    uint4 h[2], l[2];
#pragma unroll
    for (int j = 0; j < 2; j++) {
        float l0, l1, l2, l3, l4, l5, l6, l7;
        h[j].x = pack_hi2(v[2 * j].x,     v[2 * j].y,     &l0, &l1);
        h[j].y = pack_hi2(v[2 * j].z,     v[2 * j].w,     &l2, &l3);
        h[j].z = pack_hi2(v[2 * j + 1].x, v[2 * j + 1].y, &l4, &l5);
        h[j].w = pack_hi2(v[2 * j + 1].z, v[2 * j + 1].w, &l6, &l7);
        l[j].x = pack_lo2(l0, l1);
        l[j].y = pack_lo2(l2, l3);
        l[j].z = pack_lo2(l4, l5);
        l[j].w = pack_lo2(l6, l7);
    }
    uint4* ph = (uint4*)(hi + 16 * (size_t)i);
    uint4* pl = (uint4*)(lo + 16 * (size_t)i);
    ph[0] = h[0]; ph[1] = h[1];
    pl[0] = l[0]; pl[1] = l[1];
}

// fp32 -> single fp16 (for down-GEMM weights; halves write traffic)
__global__ void split16_kernel(const float* __restrict__ src,
                               __half* __restrict__ dst, int n16) {
    int i = blockIdx.x * blockDim.x + threadIdx.x;
    if (i >= n16) return;
    const float4* s = (const float4*)src + 4 * (size_t)i;
    float4 v[4];
#pragma unroll
    for (int j = 0; j < 4; j++) v[j] = s[j];
    uint4 o[2];
#pragma unroll
    for (int j = 0; j < 2; j++) {
        o[j].x = packh_lo2(v[2 * j].x,     v[2 * j].y);
        o[j].y = packh_lo2(v[2 * j].z,     v[2 * j].w);
        o[j].z = packh_lo2(v[2 * j + 1].x, v[2 * j + 1].y);
        o[j].w = packh_lo2(v[2 * j + 1].z, v[2 * j + 1].w);
    }
    uint4* pd = (uint4*)(dst + 16 * (size_t)i);
    pd[0] = o[0]; pd[1] = o[1];
}

// ===========================================================================
// Router + grouping (proven)
// ===========================================================================
__global__ void router_kernel(const float* __restrict__ x,
                              const float* __restrict__ rw,
                              float* __restrict__ scores_out) {
    int warps_per_block = blockDim.x >> 5;
    int t = blockIdx.x * warps_per_block + (threadIdx.x >> 5);
    int lane = threadIdx.x & 31;
    if (t >= T_TOK) return;

    float acc[E_NUM];
#pragma unroll
    for (int e = 0; e < E_NUM; e++) acc[e] = 0.f;

    const float* xr = x + (size_t)t * H_DIM;
    for (int k = lane; k < H_DIM; k += 32) {
        float xv = xr[k];
#pragma unroll
        for (int e = 0; e < E_NUM; e++) acc[e] += xv * rw[e * H_DIM + k];
    }
#pragma unroll
    for (int e = 0; e < E_NUM; e++) {
#pragma unroll
        for (int o = 16; o > 0; o >>= 1)
            acc[e] += __shfl_xor_sync(0xFFFFFFFFu, acc[e], o);
    }
    if (lane == 0) {
        int best = 0;
        float bv = acc[0];
#pragma unroll
        for (int e = 1; e < E_NUM; e++)
            if (acc[e] > bv) { bv = acc[e]; best = e; }
        float s = 1.f / (1.f + expf(-bv));
        g_sel[t] = best;
        g_score[t] = s;
#pragma unroll
        for (int e = 0; e < E_NUM; e++)
            scores_out[(size_t)e * T_TOK + t] = (e == best) ? s : 0.f;
    }
}

__global__ void group_kernel() {
    __shared__ int cnt[E_NUM];
    __shared__ int cur[E_NUM];
    int tid = threadIdx.x;
    if (tid < E_NUM) cnt[tid] = 0;
    __syncthreads();
    for (int t = tid; t < T_TOK; t += blockDim.x)
        atomicAdd(&cnt[g_sel[t]], 1);
    __syncthreads();
    if (tid == 0) {
        int run = 0;
        for (int e = 0; e < E_NUM; e++) {
            g_off[e] = run; cur[e] = run; run += cnt[e];
        }
        g_off[E_NUM] = run;
    }
    __syncthreads();
    for (int t = tid; t < T_TOK; t += blockDim.x) {
        int p = atomicAdd(&cur[g_sel[t]], 1);
        g_perm[p] = t;
    }
}

// ===========================================================================
// GEMM engine — R12/R16 configuration + R17 fp16 2-term down path.
//   EPI=0 (gateup): bf16 3-term, BN=64, W0=gate, W1=up;
//                   out = silu(G)*U*(score) -> fp16 hi/lo (exact to 2^-22)
//   EPI=1 (down):   fp16 2-term (A=h split fp16, W single fp16), BN=128;
//                   out (+)= A.W^T (fp32)
// BM: 128 (shared, 4m x 2n warps) or 64 (routed, 2m x 4n warps).
// 3-stage cp.async, 256 threads, 2 CTAs/SM. m fastest-varying grid axis.
// ===========================================================================
template<int KD, int EPI, bool ROUTED, int BM>
__global__ void __launch_bounds__(256, 2)
moe_gemm(const __nv_bfloat16* __restrict__ Ahi,
         const __nv_bfloat16* __restrict__ Alo,
         const __nv_bfloat16* __restrict__ W0hb,
         const __nv_bfloat16* __restrict__ W0lb,
         const __nv_bfloat16* __restrict__ W1hb,
         const __nv_bfloat16* __restrict__ W1lb,
         __half* __restrict__ OutHi,
         __half* __restrict__ OutLo,
         float* __restrict__ OutF,
         int ebase) {
    constexpr int BN    = (EPI == 0) ? 64 : 128;
    constexpr int WM    = BM / 32;
    constexpr int WN    = 8 / WM;
    constexpr int NW    = BN / WN;
    constexpr int NSUBW = NW / 8;
    constexpr int TA    = BM * 128;
    constexpr int TW    = BN * 128;
    constexpr int SBUF  = TA + ((EPI == 0) ? 2 * TW : TW);
    constexpr int NIT   = KD / 32;
    constexpr int AJ    = BM / 32;

    extern __shared__ char smem_raw[];
    __shared__ int   arow[BM];
    __shared__ int   orow[BM];
    __shared__ float sscale[BM];

    const uint32_t raw_u = smem_u32(smem_raw);
    const uint32_t smem_u = (raw_u + 127) & ~127u;

    const int tid = threadIdx.x;
    const int e = ROUTED ? (ebase + blockIdx.z) : 0;
    int start = 0, mcnt = T_TOK;
    if (ROUTED) { start = g_off[e]; mcnt = g_off[e + 1] - start; }
    const int m0 = blockIdx.x * BM;
    if (ROUTED && m0 >= mcnt) return;
    const int n0 = blockIdx.y * BN;

    size_t eo = ROUTED ? (size_t)e * ((EPI == 0) ? I_DIM : H_DIM) * KD : 0;
    const __nv_bfloat16* w0h = W0hb + eo + (size_t)n0 * KD;
    const __nv_bfloat16* w0l = (EPI == 0) ? (W0lb + eo + (size_t)n0 * KD) : nullptr;
    const __nv_bfloat16* w1h = (EPI == 0) ? (W1hb + eo + (size_t)n0 * KD) : nullptr;
    const __nv_bfloat16* w1l = (EPI == 0) ? (W1lb + eo + (size_t)n0 * KD) : nullptr;

    if (tid < BM) {
        int r = m0 + tid;
        int a = -1, o = -1;
        float sc = 1.f;
        if (r < mcnt) {
            if (EPI == 0) {
                a = ROUTED ? g_perm[start + r] : r;
                o = ROUTED ? (start + r) : r;
                if (ROUTED) sc = g_score[a];
            } else {
                a = ROUTED ? (start + r) : r;
                o = ROUTED ? g_perm[start + r] : r;
            }
        }
        arow[tid] = a; orow[tid] = o; sscale[tid] = sc;
    }
    __syncthreads();

    const int lane = tid & 31;
    const int wid  = tid >> 5;
    const int wm   = wid % WM;
    const int wn   = wid / WM;

    float accG[2][NSUBW][4];
    float accU[(EPI == 0) ? 2 : 1][(EPI == 0) ? NSUBW : 1][4];
#pragma unroll
    for (int mi = 0; mi < 2; mi++)
#pragma unroll
        for (int nj = 0; nj < NSUBW; nj++)
#pragma unroll
            for (int c = 0; c < 4; c++) accG[mi][nj][c] = 0.f;
    if (EPI == 0) {
#pragma unroll
        for (int mi = 0; mi < 2; mi++)
#pragma unroll
            for (int nj = 0; nj < NSUBW; nj++)
#pragma unroll
                for (int c = 0; c < 4; c++) accU[mi][nj][c] = 0.f;
    }

    auto prefetch = [&](int it) {
        uint32_t sAu = smem_u + (it % 3) * SBUF;
        uint32_t sW0u = sAu + TA;
        uint32_t sW1u = sW0u + TW;
        int k0 = it * 32;
#pragma unroll
        for (int j = 0; j < AJ; j++) {
            int c = tid + 256 * j;
            int row = c >> 3, blk = c & 7;
            int tok = arow[row];
            const __nv_bfloat16* base = (blk < 4) ? Ahi : Alo;
            const __nv_bfloat16* src =
                base + (size_t)(tok < 0 ? 0 : tok) * KD + k0 + (blk & 3) * 8;
            cp16(swadr(sAu, row, blk), src, tok < 0 ? 0 : 16);
        }
        if (EPI == 0) {
#pragma unroll
            for (int j = 0; j < 4; j++) {
                int c = tid + 256 * j;
                int mat = c >> 9, cc = c & 511;
                int row = cc >> 3, blk = cc & 7;
                const __nv_bfloat16* base =
                    mat ? ((blk < 4) ? w1h : w1l) : ((blk < 4) ? w0h : w0l);
                cp16(swadr(mat ? sW1u : sW0u, row, blk),
                     base + (size_t)row * KD + k0 + (blk & 3) * 8, 16);
            }
        } else {
            // Single fp16 weight: only hi blocks 0-3 (512 chunks, 2/thread).
#pragma unroll
            for (int j = 0; j < 2; j++) {
                int c = tid + 256 * j;
                int row = c >> 2, blk = c & 3;
                cp16(swadr(sW0u, row, blk),
                     w0h + (size_t)row * KD + k0 + blk * 8, 16);
            }
        }
    };

    auto compute = [&](int buf) {
        const uint32_t sA  = smem_u + buf * SBUF;
        const uint32_t sW0 = sA + TA;
        const uint32_t sW1 = sW0 + TW;
        const int lr = lane & 7;
        const int t  = lane >> 3;
#pragma unroll
        for (int kk = 0; kk < 2; kk++) {
            const int kb = 2 * kk;
            uint32_t ah[2][4], al[2][4];
#pragma unroll
            for (int mi = 0; mi < 2; mi++) {
                int row = wm * 32 + mi * 16 + (t & 1) * 8 + lr;
                int blk = kb + (t >> 1);
                ldm_x4(ah[mi], swadr(sA, row, blk));
                ldm_x4(al[mi], swadr(sA, row, blk + 4));
            }
#pragma unroll
            for (int p = 0; p < NSUBW / 2; p++) {
                int n = wn * NW + p * 16 + (t >> 1) * 8 + lr;
                int blk = kb + (t & 1);
                if (EPI == 0) {
                    uint32_t gh[4], gl[4];
                    ldm_x4(gh, swadr(sW0, n, blk));
                    ldm_x4(gl, swadr(sW0, n, blk + 4));
#pragma unroll
                    for (int mi = 0; mi < 2; mi++) {
                        mma_bf16(accG[mi][2 * p],     ah[mi], gh);
                        mma_bf16(accG[mi][2 * p],     ah[mi], gl + 0);
                        mma_bf16(accG[mi][2 * p],     al[mi], gh);
                        mma_bf16(accG[mi][2 * p + 1], ah[mi], gh + 2);
                        mma_bf16(accG[mi][2 * p + 1], ah[mi], gl + 2);
                        mma_bf16(accG[mi][2 * p + 1], al[mi], gh + 2);
                    }
                    uint32_t uh[4], ul[4];
                    ldm_x4(uh, swadr(sW1, n, blk));
                    ldm_x4(ul, swadr(sW1, n, blk + 4));
#pragma unroll
                    for (int mi = 0; mi < 2; mi++) {
                        mma_bf16(accU[mi][2 * p],     ah[mi], uh);
                        mma_bf16(accU[mi][2 * p],     ah[mi], ul + 0);
                        mma_bf16(accU[mi][2 * p],     al[mi], uh);
                        mma_bf16(accU[mi][2 * p + 1], ah[mi], uh + 2);
                        mma_bf16(accU[mi][2 * p + 1], ah[mi], ul + 2);
                        mma_bf16(accU[mi][2 * p + 1], al[mi], uh + 2);
                    }
                } else {
                    // fp16 2-term: A split (exact), W single fp16.
                    uint32_t gh[4];
                    ldm_x4(gh, swadr(sW0, n, blk));
#pragma unroll
                    for (int mi = 0; mi < 2; mi++) {
                        mma_f16(accG[mi][2 * p],     ah[mi], gh);
                        mma_f16(accG[mi][2 * p],     al[mi], gh);
                        mma_f16(accG[mi][2 * p + 1], ah[mi], gh + 2);
                        mma_f16(accG[mi][2 * p + 1], al[mi], gh + 2);
                    }
                }
            }
        }
    };

    prefetch(0); cp_commit();
    prefetch(1); cp_commit();
    for (int i = 0; i < NIT; i++) {
        if (i + 2 < NIT) cp_wait<1>(); else cp_wait<0>();
        __syncthreads();
        if (i + 2 < NIT) { prefetch(i + 2); cp_commit(); }
        compute(i % 3);
    }

#pragma unroll
    for (int mi = 0; mi < 2; mi++) {
#pragma unroll
        for (int ci = 0; ci < 2; ci++) {
            int r = wm * 32 + mi * 16 + (lane >> 2) + ci * 8;
            int o = orow[r];
            if (o < 0) continue;
            float sc = sscale[r];
#pragma unroll
            for (int nj = 0; nj < NSUBW; nj++) {
                int col = n0 + wn * NW + nj * 8 + (lane & 3) * 2;
                if (EPI == 0) {
                    float g0 = accG[mi][nj][ci * 2];
                    float g1 = accG[mi][nj][ci * 2 + 1];
                    float vx = g0 / (1.f + expf(-g0)) * accU[mi][nj][ci * 2] * sc;
                    float vy = g1 / (1.f + expf(-g1)) * accU[mi][nj][ci * 2 + 1] * sc;
                    float lx, ly;
                    uint32_t hp = packh_hi2(vx, vy, &lx, &ly);
                    uint32_t lp = packh_lo2(lx, ly);
                    *(uint32_t*)(OutHi + (size_t)o * I_DIM + col) = hp;
                    *(uint32_t*)(OutLo + (size_t)o * I_DIM + col) = lp;
                } else {
                    float2 v;
                    v.x = accG[mi][nj][ci * 2];
                    v.y = accG[mi][nj][ci * 2 + 1];
                    float* op = OutF + (size_t)o * H_DIM + col;
                    if (ROUTED) {
                        float2 old = *(float2*)op;
                        v.x += old.x; v.y += old.y;
                    }
                    *(float2*)op = v;
                }
            }
        }
    }
}

// ===========================================================================
extern "C" void kernel_launch(void* const* d_in, const int* in_sizes, int n_in,
                              void* d_out, int out_size) {
    const float* x        = (const float*)d_in[0];  // [T, H]
    const float* router_w = (const float*)d_in[1];  // [E, H]
    const float* eg_w     = (const float*)d_in[2];  // [E, I, H]
    const float* eu_w     = (const float*)d_in[3];  // [E, I, H]
    const float* ed_w     = (const float*)d_in[4];  // [E, H, I]
    const float* sg_w     = (const float*)d_in[5];  // [I, H]
    const float* su_w     = (const float*)d_in[6];  // [I, H]
    const float* sd_w     = (const float*)d_in[7];  // [H, I]

    float* out    = (float*)d_out;
    float* scores = (float*)d_out + (size_t)T_TOK * H_DIM;

    __nv_bfloat16 *x_hi, *x_lo, *eg_hi, *eg_lo, *eu_hi, *eu_lo;
    __nv_bfloat16 *sg_hi, *sg_lo, *su_hi, *su_lo;
    __half *ed16, *sd16, *hs_hi, *hs_lo, *hr_hi, *hr_lo;
    cudaGetSymbolAddress((void**)&x_hi, g_x_hi);
    cudaGetSymbolAddress((void**)&x_lo, g_x_lo);
    cudaGetSymbolAddress((void**)&eg_hi, g_eg_hi);
    cudaGetSymbolAddress((void**)&eg_lo, g_eg_lo);
    cudaGetSymbolAddress((void**)&eu_hi, g_eu_hi);
    cudaGetSymbolAddress((void**)&eu_lo, g_eu_lo);
    cudaGetSymbolAddress((void**)&sg_hi, g_sg_hi);
    cudaGetSymbolAddress((void**)&sg_lo, g_sg_lo);
    cudaGetSymbolAddress((void**)&su_hi, g_su_hi);
    cudaGetSymbolAddress((void**)&su_lo, g_su_lo);
    cudaGetSymbolAddress((void**)&ed16, g_ed16);
    cudaGetSymbolAddress((void**)&sd16, g_sd16);
    cudaGetSymbolAddress((void**)&hs_hi, g_hs_hi);
    cudaGetSymbolAddress((void**)&hs_lo, g_hs_lo);
    cudaGetSymbolAddress((void**)&hr_hi, g_hr_hi);
    cudaGetSymbolAddress((void**)&hr_lo, g_hr_lo);

    const int SMEM128 = 3 * 32768 + 128;
    const int SMEM64  = 3 * 24576 + 128;

    // One-time setup on the FIRST call (correctness run): stream/event pools
    // exist before the harness's pre-capture baseline; nothing is allocated
    // during capture or replay. Work per call is identical.
    static cudaStream_t s2 = nullptr, s3 = nullptr;
    static cudaEvent_t evFork = nullptr, evS2A = nullptr, evS2B = nullptr, evEd = nullptr;
    static cudaEvent_t evM = nullptr, ev2 = nullptr, evA = nullptr, ev3 = nullptr;
    if (s2 == nullptr) {
        cudaStreamCreateWithFlags(&s2, cudaStreamNonBlocking);
        cudaStreamCreateWithFlags(&s3, cudaStreamNonBlocking);
        cudaEventCreateWithFlags(&evFork, cudaEventDisableTiming);
        cudaEventCreateWithFlags(&evS2A,  cudaEventDisableTiming);
        cudaEventCreateWithFlags(&evS2B,  cudaEventDisableTiming);
        cudaEventCreateWithFlags(&evEd,   cudaEventDisableTiming);
        cudaEventCreateWithFlags(&evM,    cudaEventDisableTiming);
        cudaEventCreateWithFlags(&ev2,    cudaEventDisableTiming);
        cudaEventCreateWithFlags(&evA,    cudaEventDisableTiming);
        cudaEventCreateWithFlags(&ev3,    cudaEventDisableTiming);
        cudaFuncSetAttribute(moe_gemm<2048, 0, false, 128>, cudaFuncAttributeMaxDynamicSharedMemorySize, SMEM128);
        cudaFuncSetAttribute(moe_gemm<4096, 1, false, 128>, cudaFuncAttributeMaxDynamicSharedMemorySize, SMEM128);
        cudaFuncSetAttribute(moe_gemm<2048, 0, true, 64>,   cudaFuncAttributeMaxDynamicSharedMemorySize, SMEM64);
        cudaFuncSetAttribute(moe_gemm<4096, 1, true, 64>,   cudaFuncAttributeMaxDynamicSharedMemorySize, SMEM64);
    }

    auto split = [&](const float* src, __nv_bfloat16* hi, __nv_bfloat16* lo,
                     size_t n, cudaStream_t st) {
        int n16 = (int)(n / 16);
        split_kernel<<<(n16 + 255) / 256, 256, 0, st>>>(src, hi, lo, n16);
    };
    auto split16 = [&](const float* src, __half* dst, size_t n, cudaStream_t st) {
        int n16 = (int)(n / 16);
        split16_kernel<<<(n16 + 255) / 256, 256, 0, st>>>(src, dst, n16);
    };

    const size_t EG_HALF = (size_t)4 * I_DIM * H_DIM;  // experts 0-3 slice

    // ---- capture-legal fork at graph start ----
    cudaEventRecord(evFork, 0);
    cudaStreamWaitEvent(s2, evFork, 0);
    cudaStreamWaitEvent(s3, evFork, 0);

    // ---- s2: router + grouping + eg/eu splits per expert-half, then ed ----
    router_kernel<<<T_TOK / 8, 256, 0, s2>>>(x, router_w, scores);
    group_kernel<<<1, 256, 0, s2>>>();
    split(eg_w, eg_hi, eg_lo, EG_HALF, s2);
    split(eu_w, eu_hi, eu_lo, EG_HALF, s2);
    cudaEventRecord(evS2A, s2);
    split(eg_w + EG_HALF, eg_hi + EG_HALF, eg_lo + EG_HALF, EG_HALF, s2);
    split(eu_w + EG_HALF, eu_hi + EG_HALF, eu_lo + EG_HALF, EG_HALF, s2);
    cudaEventRecord(evS2B, s2);
    split16(ed_w, ed16, (size_t)E_NUM * H_DIM * I_DIM, s2);
    cudaEventRecord(evEd, s2);

    // ---- main: x/sg/su splits -> evM; main then runs the routed chain ----
    split(x,    x_hi,  x_lo,  (size_t)T_TOK * H_DIM, 0);
    split(sg_w, sg_hi, sg_lo, (size_t)I_DIM * H_DIM, 0);
    split(su_w, su_hi, su_lo, (size_t)I_DIM * H_DIM, 0);
    cudaEventRecord(evM, 0);

    // ---- s3: sd split16, then shared gate-up + shared down -> ev2 ----
    split16(sd_w, sd16, (size_t)H_DIM * I_DIM, s3);
    cudaStreamWaitEvent(s3, evM, 0);
    moe_gemm<2048, 0, false, 128><<<dim3(T_TOK / 128, I_DIM / 64), 256, SMEM128, s3>>>(
        x_hi, x_lo, sg_hi, sg_lo, su_hi, su_lo, hs_hi, hs_lo, nullptr, 0);
    moe_gemm<4096, 1, false, 128><<<dim3(T_TOK / 128, H_DIM / 128), 256, SMEM128, s3>>>(
        (const __nv_bfloat16*)hs_hi, (const __nv_bfloat16*)hs_lo,
        (const __nv_bfloat16*)sd16, nullptr, nullptr, nullptr,
        nullptr, nullptr, out, 0);
    cudaEventRecord(ev2, s3);

    // ---- main: routed gate-up A (experts 0-3), then B (4-7) ----
    cudaStreamWaitEvent(0, evS2A, 0);
    moe_gemm<2048, 0, true, 64><<<dim3(T_TOK / 64, I_DIM / 64, 4), 256, SMEM64>>>(
        x_hi, x_lo, eg_hi, eg_lo, eu_hi, eu_lo, hr_hi, hr_lo, nullptr, 0);
    cudaEventRecord(evA, 0);
    cudaStreamWaitEvent(0, evS2B, 0);
    moe_gemm<2048, 0, true, 64><<<dim3(T_TOK / 64, I_DIM / 64, 4), 256, SMEM64>>>(
        x_hi, x_lo, eg_hi, eg_lo, eu_hi, eu_lo, hr_hi, hr_lo, nullptr, 4);

    // ---- s2: routed down A — needs gate-up A (evA), ed (s2 order), ev2 ----
    cudaStreamWaitEvent(s2, evA, 0);
    cudaStreamWaitEvent(s2, ev2, 0);
    moe_gemm<4096, 1, true, 64><<<dim3(T_TOK / 64, H_DIM / 128, 4), 256, SMEM64, s2>>>(
        (const __nv_bfloat16*)hr_hi, (const __nv_bfloat16*)hr_lo,
        (const __nv_bfloat16*)ed16, nullptr, nullptr, nullptr,
        nullptr, nullptr, out, 0);
    cudaEventRecord(ev3, s2);

    // ---- main: routed down B — after gate-up B (order), evEd, ev2 ----
    cudaStreamWaitEvent(0, evEd, 0);
    cudaStreamWaitEvent(0, ev2, 0);
    moe_gemm<4096, 1, true, 64><<<dim3(T_TOK / 64, H_DIM / 128, 4), 256, SMEM64>>>(
        (const __nv_bfloat16*)hr_hi, (const __nv_bfloat16*)hr_lo,
        (const __nv_bfloat16*)ed16, nullptr, nullptr, nullptr,
        nullptr, nullptr, out, 4);

    // ---- join all side streams before capture ends ----
    cudaStreamWaitEvent(0, ev3, 0);
}